// round 1
// baseline (speedup 1.0000x reference)
#include <cuda_runtime.h>
#include <math.h>

#define BSZ 4
#define NSEQ 512
#define DIM 128
#define M_TOTAL (BSZ * NSEQ)   // 2048 rows for projections

// Scratch (no cudaMalloc allowed): q, exp(k), exp(k)*v  — 1 MB each
__device__ float g_q  [BSZ * NSEQ * DIM];
__device__ float g_ek [BSZ * NSEQ * DIM];
__device__ float g_ekv[BSZ * NSEQ * DIM];

// ---------------------------------------------------------------------------
// Kernel 1: fused projections.
// out_q = sigmoid(x @ Wq^T + bq); ek = exp(x @ Wk^T + bk); ekv = ek * (x @ Wv^T + bv)
// Grid: 64 blocks (32 rows each), 256 threads.
// Thread tile: 2 rows x 8 cols, accumulators for all 3 projections.
// ---------------------------------------------------------------------------
__global__ __launch_bounds__(256)
void proj_kernel(const float* __restrict__ x,
                 const float* __restrict__ Wq, const float* __restrict__ bq,
                 const float* __restrict__ Wk, const float* __restrict__ bk,
                 const float* __restrict__ Wv, const float* __restrict__ bv)
{
    __shared__ float x_s[32 * 16];          // [row][d] chunk (Kc = 16)
    __shared__ float w_s[3][16 * 128];      // [d][e] transposed chunks (conflict-free e-reads)

    const int tid = threadIdx.x;
    const int m0  = blockIdx.x * 32;
    const int tx  = tid & 15;               // e group: e = tx*8 + i
    const int ty  = tid >> 4;               // row group: m = m0 + ty*2 + r

    float accQ[2][8] = {}, accK[2][8] = {}, accV[2][8] = {};

    for (int kc = 0; kc < DIM; kc += 16) {
        // x chunk: 32 rows x 16 d  (512 elems, 2/thread) — coalesced 64B rows
        for (int i = tid; i < 32 * 16; i += 256) {
            int r = i >> 4, d = i & 15;
            x_s[i] = x[(m0 + r) * DIM + kc + d];
        }
        // W chunks, stored transposed w_s[d*128 + e] = W[e*DIM + kc + d]
        // (global reads strided but W is tiny and L2-resident; smem reads conflict-free)
        for (int i = tid; i < 16 * 128; i += 256) {
            int dd = i >> 7, e = i & 127;
            int gidx = e * DIM + kc + dd;
            w_s[0][i] = Wq[gidx];
            w_s[1][i] = Wk[gidx];
            w_s[2][i] = Wv[gidx];
        }
        __syncthreads();

        #pragma unroll
        for (int d = 0; d < 16; ++d) {
            float xv0 = x_s[(ty * 2 + 0) * 16 + d];
            float xv1 = x_s[(ty * 2 + 1) * 16 + d];
            #pragma unroll
            for (int i = 0; i < 8; ++i) {
                int e = tx * 8 + i;
                float wq = w_s[0][d * 128 + e];
                float wk = w_s[1][d * 128 + e];
                float wv = w_s[2][d * 128 + e];
                accQ[0][i] += xv0 * wq;  accQ[1][i] += xv1 * wq;
                accK[0][i] += xv0 * wk;  accK[1][i] += xv1 * wk;
                accV[0][i] += xv0 * wv;  accV[1][i] += xv1 * wv;
            }
        }
        __syncthreads();
    }

    // Epilogue: bias + nonlinearities, write scratch
    #pragma unroll
    for (int r = 0; r < 2; ++r) {
        int m = m0 + ty * 2 + r;
        #pragma unroll
        for (int i = 0; i < 8; ++i) {
            int e = tx * 8 + i;
            float qv = accQ[r][i] + bq[e];
            float kv = accK[r][i] + bk[e];
            float vv = accV[r][i] + bv[e];
            float sq = 1.0f / (1.0f + expf(-qv));
            float ek = expf(kv);
            g_q  [m * DIM + e] = sq;
            g_ek [m * DIM + e] = ek;
            g_ekv[m * DIM + e] = ek * vv;
        }
    }
}

// ---------------------------------------------------------------------------
// Kernel 2: AFT core.
//   num[b,t,d] = sum_j exp(pb[t,j]) * ekv[b,j,d]
//   den[b,t,d] = sum_j exp(pb[t,j]) * ek [b,j,d]
//   out[b,t,d] = q[b,t,d] * num / den
// Grid: (16 t-tiles of 32, 2 d-tiles of 64, 4 batches) = 128 blocks, 256 thr.
// Thread tile: 2 t x 4 d, dual accumulators (num & den).
// exp(pos_bias) computed on-the-fly during smem staging (no extra pass).
// ---------------------------------------------------------------------------
__global__ __launch_bounds__(256)
void aft_kernel(const float* __restrict__ pos_bias, float* __restrict__ out)
{
    __shared__ float w_s[32][33];           // [t][j], padded vs 4-way conflicts
    __shared__ float ekv_s[32][64];         // [j][d]
    __shared__ float ek_s [32][64];

    const int tid = threadIdx.x;
    const int t0  = blockIdx.x * 32;
    const int d0  = blockIdx.y * 64;
    const int b   = blockIdx.z;

    const int tx = tid & 15;                // d = d0 + tx*4 + c
    const int ty = tid >> 4;                // t = t0 + ty*2 + r

    const float* __restrict__ ek_b  = g_ek  + b * NSEQ * DIM;
    const float* __restrict__ ekv_b = g_ekv + b * NSEQ * DIM;

    float accN[2][4] = {}, accD[2][4] = {};

    for (int j0 = 0; j0 < NSEQ; j0 += 32) {
        // stage exp(pos_bias) tile: 32t x 32j, coalesced in j
        for (int i = tid; i < 32 * 32; i += 256) {
            int t = i >> 5, j = i & 31;
            w_s[t][j] = expf(pos_bias[(t0 + t) * NSEQ + j0 + j]);
        }
        // stage ek / ekv tiles: 32j x 64d, coalesced 256B rows
        for (int i = tid; i < 32 * 64; i += 256) {
            int j = i >> 6, d = i & 63;
            int gidx = (j0 + j) * DIM + d0 + d;
            ek_s [j][d] = ek_b [gidx];
            ekv_s[j][d] = ekv_b[gidx];
        }
        __syncthreads();

        #pragma unroll
        for (int j = 0; j < 32; ++j) {
            float w0 = w_s[ty * 2 + 0][j];
            float w1 = w_s[ty * 2 + 1][j];
            float4 kv = *reinterpret_cast<const float4*>(&ekv_s[j][tx * 4]);
            float4 kk = *reinterpret_cast<const float4*>(&ek_s [j][tx * 4]);
            accN[0][0] += w0 * kv.x;  accN[0][1] += w0 * kv.y;
            accN[0][2] += w0 * kv.z;  accN[0][3] += w0 * kv.w;
            accN[1][0] += w1 * kv.x;  accN[1][1] += w1 * kv.y;
            accN[1][2] += w1 * kv.z;  accN[1][3] += w1 * kv.w;
            accD[0][0] += w0 * kk.x;  accD[0][1] += w0 * kk.y;
            accD[0][2] += w0 * kk.z;  accD[0][3] += w0 * kk.w;
            accD[1][0] += w1 * kk.x;  accD[1][1] += w1 * kk.y;
            accD[1][2] += w1 * kk.z;  accD[1][3] += w1 * kk.w;
        }
        __syncthreads();
    }

    // Epilogue: out = q * num/den
    #pragma unroll
    for (int r = 0; r < 2; ++r) {
        int t = t0 + ty * 2 + r;
        #pragma unroll
        for (int c = 0; c < 4; ++c) {
            int d = d0 + tx * 4 + c;
            int gidx = (b * NSEQ + t) * DIM + d;
            out[gidx] = g_q[gidx] * (accN[r][c] / accD[r][c]);
        }
    }
}

// ---------------------------------------------------------------------------
extern "C" void kernel_launch(void* const* d_in, const int* in_sizes, int n_in,
                              void* d_out, int out_size)
{
    const float* x        = (const float*)d_in[0];
    const float* Wq       = (const float*)d_in[1];
    const float* bq       = (const float*)d_in[2];
    const float* Wk       = (const float*)d_in[3];
    const float* bk       = (const float*)d_in[4];
    const float* Wv       = (const float*)d_in[5];
    const float* bv       = (const float*)d_in[6];
    const float* pos_bias = (const float*)d_in[7];
    float* out = (float*)d_out;

    proj_kernel<<<M_TOTAL / 32, 256>>>(x, Wq, bq, Wk, bk, Wv, bv);
    aft_kernel<<<dim3(NSEQ / 32, DIM / 64, BSZ), 256>>>(pos_bias, out);
}

// round 4
// speedup vs baseline: 2.2262x; 2.2262x over previous
#include <cuda_runtime.h>
#include <math.h>

#define BSZ  4
#define NSEQ 512
#define DIM  128
#define MROWS (BSZ * NSEQ)      // 2048
#define NSPLIT 4                // j-splits for the AFT GEMM
#define JCHUNK (NSEQ / NSPLIT)  // 128

// ---- scratch (__device__ globals; no cudaMalloc allowed) -------------------
__device__ float g_q   [MROWS * DIM];   // sigmoid(x Wq^T + bq)
__device__ float g_ek  [MROWS * DIM];   // exp(x Wk^T + bk)
__device__ float g_vraw[MROWS * DIM];   // x Wv^T + bv
__device__ float g_ekv [MROWS * DIM];   // ek * vraw
__device__ float g_w   [NSEQ * NSEQ];   // exp(pos_bias)
__device__ float g_part[NSPLIT * BSZ * 2 * NSEQ * DIM];  // partial num/den (8MB)

// ---------------------------------------------------------------------------
// Kernel 1: projections as one GEMM  Y[2048, 3*128] = x @ Wcat^T (+bias, act)
// Grid (32 r-tiles, 3 matrices). Block tile 64r x 128c, 256 thr, thread 4x8.
// W staged TRANSPOSED through smem with coalesced global reads.
// ---------------------------------------------------------------------------
__global__ __launch_bounds__(256)
void proj_kernel(const float* __restrict__ x,
                 const float* __restrict__ Wq, const float* __restrict__ bq,
                 const float* __restrict__ Wk, const float* __restrict__ bk,
                 const float* __restrict__ Wv, const float* __restrict__ bv)
{
    __shared__ float x_s[64][36];     // [r][k]
    __shared__ float w_s[32][136];    // [k][c] = W[c][k0+k]  (transposed)

    const int m  = blockIdx.y;        // 0:q 1:k 2:v
    const float* __restrict__ W    = (m == 0) ? Wq : (m == 1) ? Wk : Wv;
    const float* __restrict__ bias = (m == 0) ? bq : (m == 1) ? bk : bv;
    float* __restrict__ outp       = (m == 0) ? g_q : (m == 1) ? g_ek : g_vraw;

    const int tid = threadIdx.x;
    const int tx  = tid & 15;         // c = tx*8 + j
    const int ty  = tid >> 4;         // r = r0 + ty*4 + i
    const int r0  = blockIdx.x * 64;

    float acc[4][8] = {};

    for (int k0 = 0; k0 < DIM; k0 += 32) {
        // x tile: 64r x 32k, coalesced 128B rows
        for (int i = tid; i < 64 * 32; i += 256) {
            int r = i >> 5, kk = i & 31;
            x_s[r][kk] = x[(r0 + r) * DIM + k0 + kk];
        }
        // W tile transposed: coalesced reads of W rows, strided smem store
        for (int i = tid; i < 128 * 32; i += 256) {
            int c = i >> 5, kk = i & 31;
            w_s[kk][c] = W[c * DIM + k0 + kk];
        }
        __syncthreads();

        #pragma unroll
        for (int kk = 0; kk < 32; ++kk) {
            float xv[4];
            #pragma unroll
            for (int i = 0; i < 4; ++i) xv[i] = x_s[ty * 4 + i][kk];
            float4 wa = *reinterpret_cast<const float4*>(&w_s[kk][tx * 8]);
            float4 wb = *reinterpret_cast<const float4*>(&w_s[kk][tx * 8 + 4]);
            float wr[8] = {wa.x, wa.y, wa.z, wa.w, wb.x, wb.y, wb.z, wb.w};
            #pragma unroll
            for (int i = 0; i < 4; ++i)
                #pragma unroll
                for (int j = 0; j < 8; ++j)
                    acc[i][j] += xv[i] * wr[j];
        }
        __syncthreads();
    }

    // epilogue: bias + per-matrix activation, float4 stores
    #pragma unroll
    for (int i = 0; i < 4; ++i) {
        int r = r0 + ty * 4 + i;
        float res[8];
        #pragma unroll
        for (int j = 0; j < 8; ++j) {
            float v = acc[i][j] + bias[tx * 8 + j];
            if (m == 0)      v = 1.0f / (1.0f + expf(-v));
            else if (m == 1) v = expf(v);
            res[j] = v;
        }
        float4* dst = reinterpret_cast<float4*>(&outp[r * DIM + tx * 8]);
        dst[0] = make_float4(res[0], res[1], res[2], res[3]);
        dst[1] = make_float4(res[4], res[5], res[6], res[7]);
    }
}

// ---------------------------------------------------------------------------
// Kernel 2: prep — g_w = exp(pos_bias), g_ekv = g_ek * g_vraw (elementwise)
// 131072 float4 items; grid 512 x 256.
// ---------------------------------------------------------------------------
__global__ __launch_bounds__(256)
void prep_kernel(const float* __restrict__ pos_bias)
{
    int i = blockIdx.x * 256 + threadIdx.x;
    const int NW = NSEQ * NSEQ / 4;       // 65536 float4 of pos_bias
    if (i < NW) {
        float4 p = reinterpret_cast<const float4*>(pos_bias)[i];
        float4 r = make_float4(expf(p.x), expf(p.y), expf(p.z), expf(p.w));
        reinterpret_cast<float4*>(g_w)[i] = r;
    } else {
        int j = i - NW;                    // 65536 float4 of ek/vraw
        float4 e = reinterpret_cast<const float4*>(g_ek)[j];
        float4 v = reinterpret_cast<const float4*>(g_vraw)[j];
        reinterpret_cast<float4*>(g_ekv)[j] =
            make_float4(e.x * v.x, e.y * v.y, e.z * v.z, e.w * v.w);
    }
}

// ---------------------------------------------------------------------------
// Kernel 3: AFT core GEMM with 4-way j-split.
//   P[s][b][ct][t][d] = sum_{j in chunk s} g_w[t][j] * M[b][j][d]
//   M = g_ekv (ct=0, numerator) or g_ek (ct=1, denominator)
// Grid 128 blocks: x = s + 4*(b + 4*(ct + 2*tt)). Block tile 128t x 128d,
// 256 thr, thread tile 8x8 (64 accumulators) — smem/FMA balanced at 1.0 B/FMA.
// ---------------------------------------------------------------------------
__global__ __launch_bounds__(256)
void aft_kernel()
{
    __shared__ float w_s[128][36];    // [t][kk]  (rows 144B, float4-aligned)
    __shared__ float m_s[32][136];    // [kk][d]

    const int bx = blockIdx.x;
    const int s  = bx & 3;
    const int b  = (bx >> 2) & 3;
    const int ct = (bx >> 4) & 1;
    const int tt = bx >> 5;

    const int t0 = tt * 128;
    const int j0 = s * JCHUNK;
    const float* __restrict__ M =
        (ct == 0 ? g_ekv : g_ek) + b * NSEQ * DIM;

    const int tid = threadIdx.x;
    const int tx  = tid & 15;         // d = tx*8 + j
    const int ty  = tid >> 4;         // t = t0 + ty*8 + i

    float acc[8][8] = {};

    for (int jc = 0; jc < JCHUNK; jc += 32) {
        int jb = j0 + jc;
        // stage w tile 128t x 32j (coalesced 128B rows, row-contig STS)
        for (int i = tid; i < 128 * 32; i += 256) {
            int t = i >> 5, kk = i & 31;
            w_s[t][kk] = g_w[(t0 + t) * NSEQ + jb + kk];
        }
        // stage M tile 32j x 128d (coalesced, row-contig STS)
        for (int i = tid; i < 32 * 128; i += 256) {
            int kk = i >> 7, d = i & 127;
            m_s[kk][d] = M[(jb + kk) * DIM + d];
        }
        __syncthreads();

        #pragma unroll
        for (int kk = 0; kk < 32; kk += 4) {
            float4 wv[8];
            #pragma unroll
            for (int i = 0; i < 8; ++i)
                wv[i] = *reinterpret_cast<const float4*>(&w_s[ty * 8 + i][kk]);
            #pragma unroll
            for (int u = 0; u < 4; ++u) {
                float4 ma = *reinterpret_cast<const float4*>(&m_s[kk + u][tx * 8]);
                float4 mb = *reinterpret_cast<const float4*>(&m_s[kk + u][tx * 8 + 4]);
                float mr[8] = {ma.x, ma.y, ma.z, ma.w, mb.x, mb.y, mb.z, mb.w};
                #pragma unroll
                for (int i = 0; i < 8; ++i) {
                    float w = (u == 0) ? wv[i].x : (u == 1) ? wv[i].y
                            : (u == 2) ? wv[i].z : wv[i].w;
                    #pragma unroll
                    for (int j = 0; j < 8; ++j)
                        acc[i][j] += w * mr[j];
                }
            }
        }
        __syncthreads();
    }

    // write partials (float4)
    float* base = g_part + (((size_t)(s * BSZ + b) * 2 + ct) * NSEQ) * DIM;
    #pragma unroll
    for (int i = 0; i < 8; ++i) {
        int t = t0 + ty * 8 + i;
        float4* dst = reinterpret_cast<float4*>(&base[t * DIM + tx * 8]);
        dst[0] = make_float4(acc[i][0], acc[i][1], acc[i][2], acc[i][3]);
        dst[1] = make_float4(acc[i][4], acc[i][5], acc[i][6], acc[i][7]);
    }
}

// ---------------------------------------------------------------------------
// Kernel 4: reduce — out = q * (sum_s num) / (sum_s den)
// 65536 float4 outputs; grid 256 x 256.
// ---------------------------------------------------------------------------
__global__ __launch_bounds__(256)
void reduce_kernel(float* __restrict__ out)
{
    int i = blockIdx.x * 256 + threadIdx.x;     // float4 index over [b][t][d]
    const int PER_B = NSEQ * DIM / 4;           // 16384
    int b  = i / PER_B;
    int td = i - b * PER_B;

    float4 num = make_float4(0.f, 0.f, 0.f, 0.f);
    float4 den = make_float4(0.f, 0.f, 0.f, 0.f);
    #pragma unroll
    for (int s = 0; s < NSPLIT; ++s) {
        const float4* pn = reinterpret_cast<const float4*>(
            g_part + ((size_t)(s * BSZ + b) * 2 + 0) * NSEQ * DIM) + td;
        const float4* pd = reinterpret_cast<const float4*>(
            g_part + ((size_t)(s * BSZ + b) * 2 + 1) * NSEQ * DIM) + td;
        float4 n = *pn, d = *pd;
        num.x += n.x; num.y += n.y; num.z += n.z; num.w += n.w;
        den.x += d.x; den.y += d.y; den.z += d.z; den.w += d.w;
    }
    float4 q = reinterpret_cast<const float4*>(g_q)[i];
    reinterpret_cast<float4*>(out)[i] = make_float4(
        q.x * (num.x / den.x), q.y * (num.y / den.y),
        q.z * (num.z / den.z), q.w * (num.w / den.w));
}

// ---------------------------------------------------------------------------
extern "C" void kernel_launch(void* const* d_in, const int* in_sizes, int n_in,
                              void* d_out, int out_size)
{
    const float* x        = (const float*)d_in[0];
    const float* Wq       = (const float*)d_in[1];
    const float* bq       = (const float*)d_in[2];
    const float* Wk       = (const float*)d_in[3];
    const float* bk       = (const float*)d_in[4];
    const float* Wv       = (const float*)d_in[5];
    const float* bv       = (const float*)d_in[6];
    const float* pos_bias = (const float*)d_in[7];
    float* out = (float*)d_out;

    proj_kernel<<<dim3(32, 3), 256>>>(x, Wq, bq, Wk, bk, Wv, bv);
    prep_kernel<<<512, 256>>>(pos_bias);
    aft_kernel<<<128, 256>>>();
    reduce_kernel<<<256, 256>>>(out);
}

// round 8
// speedup vs baseline: 2.6854x; 1.2063x over previous
#include <cuda_runtime.h>
#include <cuda_bf16.h>
#include <math.h>
#include <stdint.h>

#define BSZ  4
#define NSEQ 512
#define DIM  128
#define MROWS (BSZ * NSEQ)      // 2048

// ---- scratch (__device__ globals; no cudaMalloc allowed) -------------------
__device__ float g_q   [MROWS * DIM];   // sigmoid(x Wq^T + bq)
__device__ float g_ek  [MROWS * DIM];   // exp(x Wk^T + bk)
__device__ float g_vraw[MROWS * DIM];   // x Wv^T + bv
__device__ float g_num [MROWS * DIM];   // sum_j w[t][j] ekv[j][d]
__device__ float g_den [MROWS * DIM];   // sum_j w[t][j] ek [j][d]

// pre-split bf16 operands (uint4-typed for 16B alignment)
__device__ uint4 g_wh   [NSEQ * NSEQ / 8];     // bf16 hi of exp(pos_bias) [t][j]
__device__ uint4 g_wl   [NSEQ * NSEQ / 8];     // bf16 lo
__device__ uint4 g_ekvTh[BSZ * DIM * NSEQ / 8];// bf16 hi of (ek*v)^T [b][d][j]
__device__ uint4 g_ekvTl[BSZ * DIM * NSEQ / 8];
__device__ uint4 g_ekTh [BSZ * DIM * NSEQ / 8];// bf16 hi of ek^T [b][d][j]
__device__ uint4 g_ekTl [BSZ * DIM * NSEQ / 8];

// ---------------------------------------------------------------------------
// helpers
// ---------------------------------------------------------------------------
__device__ __forceinline__ uint32_t smem_u32(const void* p) {
    uint32_t a;
    asm("{ .reg .u64 t; cvta.to.shared.u64 t, %1; cvt.u32.u64 %0, t; }"
        : "=r"(a) : "l"(p));
    return a;
}
#define LDSM_X4(r0, r1, r2, r3, addr) \
    asm volatile("ldmatrix.sync.aligned.m8n8.x4.shared.b16 {%0,%1,%2,%3}, [%4];" \
        : "=r"(r0), "=r"(r1), "=r"(r2), "=r"(r3) : "r"(addr))

#define MMA16816(d, a, b0, b1) \
    asm volatile("mma.sync.aligned.m16n8k16.row.col.f32.bf16.bf16.f32 " \
        "{%0,%1,%2,%3}, {%4,%5,%6,%7}, {%8,%9}, {%0,%1,%2,%3};" \
        : "+f"((d)[0]), "+f"((d)[1]), "+f"((d)[2]), "+f"((d)[3]) \
        : "r"((a)[0]), "r"((a)[1]), "r"((a)[2]), "r"((a)[3]), \
          "r"(b0), "r"(b1))

__device__ __forceinline__ void bsplit(float x, unsigned short& h, unsigned short& l) {
    __nv_bfloat16 hb = __float2bfloat16(x);
    __nv_bfloat16 lb = __float2bfloat16(x - __bfloat162float(hb));
    h = __bfloat16_as_ushort(hb);
    l = __bfloat16_as_ushort(lb);
}

// ---------------------------------------------------------------------------
// Kernel 1: projections (unchanged — working fp32 GEMM)
// ---------------------------------------------------------------------------
__global__ __launch_bounds__(256)
void proj_kernel(const float* __restrict__ x,
                 const float* __restrict__ Wq, const float* __restrict__ bq,
                 const float* __restrict__ Wk, const float* __restrict__ bk,
                 const float* __restrict__ Wv, const float* __restrict__ bv)
{
    __shared__ float x_s[64][36];
    __shared__ float w_s[32][136];

    const int m  = blockIdx.y;
    const float* __restrict__ W    = (m == 0) ? Wq : (m == 1) ? Wk : Wv;
    const float* __restrict__ bias = (m == 0) ? bq : (m == 1) ? bk : bv;
    float* __restrict__ outp       = (m == 0) ? g_q : (m == 1) ? g_ek : g_vraw;

    const int tid = threadIdx.x;
    const int tx  = tid & 15;
    const int ty  = tid >> 4;
    const int r0  = blockIdx.x * 64;

    float acc[4][8] = {};

    for (int k0 = 0; k0 < DIM; k0 += 32) {
        for (int i = tid; i < 64 * 32; i += 256) {
            int r = i >> 5, kk = i & 31;
            x_s[r][kk] = x[(r0 + r) * DIM + k0 + kk];
        }
        for (int i = tid; i < 128 * 32; i += 256) {
            int c = i >> 5, kk = i & 31;
            w_s[kk][c] = W[c * DIM + k0 + kk];
        }
        __syncthreads();

        #pragma unroll
        for (int kk = 0; kk < 32; ++kk) {
            float xv[4];
            #pragma unroll
            for (int i = 0; i < 4; ++i) xv[i] = x_s[ty * 4 + i][kk];
            float4 wa = *reinterpret_cast<const float4*>(&w_s[kk][tx * 8]);
            float4 wb = *reinterpret_cast<const float4*>(&w_s[kk][tx * 8 + 4]);
            float wr[8] = {wa.x, wa.y, wa.z, wa.w, wb.x, wb.y, wb.z, wb.w};
            #pragma unroll
            for (int i = 0; i < 4; ++i)
                #pragma unroll
                for (int j = 0; j < 8; ++j)
                    acc[i][j] += xv[i] * wr[j];
        }
        __syncthreads();
    }

    #pragma unroll
    for (int i = 0; i < 4; ++i) {
        int r = r0 + ty * 4 + i;
        float res[8];
        #pragma unroll
        for (int j = 0; j < 8; ++j) {
            float v = acc[i][j] + bias[tx * 8 + j];
            if (m == 0)      v = 1.0f / (1.0f + expf(-v));
            else if (m == 1) v = expf(v);
            res[j] = v;
        }
        float4* dst = reinterpret_cast<float4*>(&outp[r * DIM + tx * 8]);
        dst[0] = make_float4(res[0], res[1], res[2], res[3]);
        dst[1] = make_float4(res[4], res[5], res[6], res[7]);
    }
}

// ---------------------------------------------------------------------------
// Kernel 2a: w prep — g_wh/g_wl = bf16 hi/lo split of exp(pos_bias).
// ---------------------------------------------------------------------------
__global__ __launch_bounds__(256)
void prep_w_kernel(const float* __restrict__ pos_bias)
{
    int i = blockIdx.x * 256 + threadIdx.x;          // 131072 float2 items
    float2 p = reinterpret_cast<const float2*>(pos_bias)[i];
    float e0 = expf(p.x), e1 = expf(p.y);
    unsigned short h0, l0, h1, l1;
    bsplit(e0, h0, l0);
    bsplit(e1, h1, l1);
    reinterpret_cast<uint32_t*>(g_wh)[i] = ((uint32_t)h1 << 16) | h0;
    reinterpret_cast<uint32_t*>(g_wl)[i] = ((uint32_t)l1 << 16) | l0;
}

// ---------------------------------------------------------------------------
// Kernel 2b: M prep — transpose ek / ekv to [b][d][j] with bf16 hi/lo split.
// ---------------------------------------------------------------------------
__global__ __launch_bounds__(256)
void prep_mt_kernel()
{
    __shared__ float s_ek[32][33], s_v[32][33];
    const int bx = blockIdx.x;
    const int jt = bx & 15, dt = (bx >> 4) & 3, b = bx >> 6;
    const int j0 = jt * 32, d0 = dt * 32;
    const int tid = threadIdx.x;

    const float* __restrict__ ekp = g_ek   + b * NSEQ * DIM;
    const float* __restrict__ vp  = g_vraw + b * NSEQ * DIM;

    for (int i = tid; i < 1024; i += 256) {
        int jj = i >> 5, dd = i & 31;
        s_ek[jj][dd] = ekp[(j0 + jj) * DIM + d0 + dd];
        s_v [jj][dd] = vp [(j0 + jj) * DIM + d0 + dd];
    }
    __syncthreads();

    for (int i = tid; i < 512; i += 256) {             // (dd, j-pair) items
        int dd = i >> 4, jj = (i & 15) * 2;
        float ek0 = s_ek[jj][dd],     ek1 = s_ek[jj + 1][dd];
        float v0  = s_v [jj][dd],     v1  = s_v [jj + 1][dd];
        float ekv0 = ek0 * v0, ekv1 = ek1 * v1;
        unsigned short kh0, kl0, kh1, kl1, vh0, vl0, vh1, vl1;
        bsplit(ek0,  kh0, kl0);  bsplit(ek1,  kh1, kl1);
        bsplit(ekv0, vh0, vl0);  bsplit(ekv1, vh1, vl1);
        uint32_t u32i = (((b * DIM + d0 + dd) * NSEQ) + j0 + jj) >> 1;
        reinterpret_cast<uint32_t*>(g_ekTh )[u32i] = ((uint32_t)kh1 << 16) | kh0;
        reinterpret_cast<uint32_t*>(g_ekTl )[u32i] = ((uint32_t)kl1 << 16) | kl0;
        reinterpret_cast<uint32_t*>(g_ekvTh)[u32i] = ((uint32_t)vh1 << 16) | vh0;
        reinterpret_cast<uint32_t*>(g_ekvTl)[u32i] = ((uint32_t)vl1 << 16) | vl0;
    }
}

// ---------------------------------------------------------------------------
// Kernel 3: AFT core on mma.sync bf16 (m16n8k16), hi/lo 3-product accumulate.
// C[t, n] = sum_j A[t][j] * B[n][j]  (A row-major, B "col" = [n][j] row-major)
// Block: 64t x 64n, K = 512 in 16 chunks of 32. 8 warps, warp tile 32t x 16n.
// Grid 128 = b(4) x tt(8) x {num,den}(2) x dh(2). Register-prefetch pipeline.
// ---------------------------------------------------------------------------
#define SA_HI 0
#define SA_LO 5120
#define SB_HI 10240
#define SB_LO 15360
#define HLOFF 5120               // lo array = hi array + 5120 (both A and B)
#define RSTRIDE 80               // 40 bf16 per row (64B data + 16B pad)

__global__ __launch_bounds__(256)
void aft_mma_kernel()
{
    __shared__ __align__(16) char sm[20480];
    const uint32_t smem = smem_u32(sm);

    const int tid  = threadIdx.x;
    const int wid  = tid >> 5, lane = tid & 31;
    const int bx   = blockIdx.x;
    const int b    = bx & 3;
    const int tt   = (bx >> 2) & 7;
    const int qq   = bx >> 5;            // 0..3
    const int ct   = qq >> 1;            // 0 = num (ekv), 1 = den (ek)
    const int dh   = qq & 1;
    const int t0   = tt * 64;
    const int d0   = dh * 64;

    const uint4* __restrict__ Ah = g_wh;
    const uint4* __restrict__ Al = g_wl;
    const uint4* __restrict__ Bh = ct ? g_ekTh : g_ekvTh;
    const uint4* __restrict__ Bl = ct ? g_ekTl : g_ekvTl;
    float* __restrict__ outp     = ct ? g_den  : g_num;

    // staging: 256 threads = 64 rows x 4 segs of uint4 (32 bf16/row chunk)
    const int srow = tid >> 2, sseg = tid & 3;
    const uint32_t soff = (uint32_t)(srow * RSTRIDE + sseg * 16);
    const int a_g = (t0 + srow) * (NSEQ / 8) + sseg;           // + c*4
    const int b_g = (b * DIM + d0 + srow) * (NSEQ / 8) + sseg; // + c*4

    // warp tiling: wm in {0,1} (32 t), wn in {0..3} (16 n)
    const int wm = wid & 1, wn = wid >> 1;
    const int r  = lane & 7, sel = lane >> 3;

    // ldmatrix lane addresses (constant across chunks)
    // A x4: lanes 0-7 rows+0 col0 | 8-15 rows+8 col0 | 16-23 rows+0 col16B | 24-31 rows+8 col16B
    uint32_t aoff[2][2];   // [mt][ks]
    #pragma unroll
    for (int mt = 0; mt < 2; ++mt)
        #pragma unroll
        for (int ks = 0; ks < 2; ++ks) {
            int row = wm * 32 + mt * 16 + r + (sel & 1) * 8;
            aoff[mt][ks] = smem + SA_HI + row * RSTRIDE + ((sel >> 1) * 16) + ks * 32;
        }
    // B x4: lanes 0-7 n+0 col0 | 8-15 n+0 col16B | 16-23 n+8 col0 | 24-31 n+8 col16B
    uint32_t boff[2];      // [ks]
    #pragma unroll
    for (int ks = 0; ks < 2; ++ks) {
        int row = wn * 16 + r + (sel >> 1) * 8;
        boff[ks] = smem + SB_HI + row * RSTRIDE + ((sel & 1) * 16) + ks * 32;
    }

    float acc[2][2][4] = {};   // [mt][nt][4]

    // prefetch chunk 0
    uint4 pAh = Ah[a_g], pAl = Al[a_g], pBh = Bh[b_g], pBl = Bl[b_g];

    for (int c = 0; c < 16; ++c) {
        // store prefetched chunk
        *reinterpret_cast<uint4*>(sm + SA_HI + soff) = pAh;
        *reinterpret_cast<uint4*>(sm + SA_LO + soff) = pAl;
        *reinterpret_cast<uint4*>(sm + SB_HI + soff) = pBh;
        *reinterpret_cast<uint4*>(sm + SB_LO + soff) = pBl;
        __syncthreads();

        // prefetch next chunk (overlaps with MMA below)
        if (c < 15) {
            int gi = (c + 1) * 4;
            pAh = Ah[a_g + gi];  pAl = Al[a_g + gi];
            pBh = Bh[b_g + gi];  pBl = Bl[b_g + gi];
        }

        #pragma unroll
        for (int ks = 0; ks < 2; ++ks) {
            uint32_t aH[2][4], aL[2][4], bH[4], bL[4];
            LDSM_X4(aH[0][0], aH[0][1], aH[0][2], aH[0][3], aoff[0][ks]);
            LDSM_X4(aH[1][0], aH[1][1], aH[1][2], aH[1][3], aoff[1][ks]);
            LDSM_X4(aL[0][0], aL[0][1], aL[0][2], aL[0][3], aoff[0][ks] + HLOFF);
            LDSM_X4(aL[1][0], aL[1][1], aL[1][2], aL[1][3], aoff[1][ks] + HLOFF);
            LDSM_X4(bH[0], bH[1], bH[2], bH[3], boff[ks]);
            LDSM_X4(bL[0], bL[1], bL[2], bL[3], boff[ks] + HLOFF);

            #pragma unroll
            for (int mt = 0; mt < 2; ++mt)
                #pragma unroll
                for (int nt = 0; nt < 2; ++nt) {
                    MMA16816(acc[mt][nt], aH[mt], bH[nt * 2], bH[nt * 2 + 1]);
                    MMA16816(acc[mt][nt], aH[mt], bL[nt * 2], bL[nt * 2 + 1]);
                    MMA16816(acc[mt][nt], aL[mt], bH[nt * 2], bH[nt * 2 + 1]);
                }
        }
        __syncthreads();
    }

    // epilogue: D fragment lane mapping: g = lane>>2, cols 2t, 2t+1
    const int g  = lane >> 2;
    const int t2 = (lane & 3) * 2;
    #pragma unroll
    for (int mt = 0; mt < 2; ++mt)
        #pragma unroll
        for (int nt = 0; nt < 2; ++nt) {
            int trow = t0 + wm * 32 + mt * 16 + g;
            int dcol = d0 + wn * 16 + nt * 8 + t2;
            size_t base = ((size_t)(b * NSEQ + trow)) * DIM + dcol;
            *reinterpret_cast<float2*>(&outp[base]) =
                make_float2(acc[mt][nt][0], acc[mt][nt][1]);
            *reinterpret_cast<float2*>(&outp[base + 8 * DIM]) =
                make_float2(acc[mt][nt][2], acc[mt][nt][3]);
        }
}

// ---------------------------------------------------------------------------
// Kernel 4: finalize — out = q * num / den (65536 float4)
// ---------------------------------------------------------------------------
__global__ __launch_bounds__(256)
void finalize_kernel(float* __restrict__ out)
{
    int i = blockIdx.x * 256 + threadIdx.x;
    float4 n = reinterpret_cast<const float4*>(g_num)[i];
    float4 d = reinterpret_cast<const float4*>(g_den)[i];
    float4 q = reinterpret_cast<const float4*>(g_q)[i];
    reinterpret_cast<float4*>(out)[i] = make_float4(
        q.x * (n.x / d.x), q.y * (n.y / d.y),
        q.z * (n.z / d.z), q.w * (n.w / d.w));
}

// ---------------------------------------------------------------------------
extern "C" void kernel_launch(void* const* d_in, const int* in_sizes, int n_in,
                              void* d_out, int out_size)
{
    const float* x        = (const float*)d_in[0];
    const float* Wq       = (const float*)d_in[1];
    const float* bq       = (const float*)d_in[2];
    const float* Wk       = (const float*)d_in[3];
    const float* bk       = (const float*)d_in[4];
    const float* Wv       = (const float*)d_in[5];
    const float* bv       = (const float*)d_in[6];
    const float* pos_bias = (const float*)d_in[7];
    float* out = (float*)d_out;

    proj_kernel<<<dim3(32, 3), 256>>>(x, Wq, bq, Wk, bk, Wv, bv);
    prep_w_kernel<<<512, 256>>>(pos_bias);
    prep_mt_kernel<<<256, 256>>>();
    aft_mma_kernel<<<128, 256>>>();
    finalize_kernel<<<256, 256>>>(out);
}

// round 11
// speedup vs baseline: 4.0252x; 1.4989x over previous
#include <cuda_runtime.h>
#include <cuda_bf16.h>
#include <math.h>
#include <stdint.h>

#define BSZ  4
#define NSEQ 512
#define DIM  128
#define MROWS (BSZ * NSEQ)      // 2048

// ---- scratch (__device__ globals; no cudaMalloc allowed) -------------------
__device__ float g_q   [MROWS * DIM];
__device__ float g_ek  [MROWS * DIM];
__device__ float g_vraw[MROWS * DIM];
__device__ float g_num [MROWS * DIM];
__device__ float g_den [MROWS * DIM];

// bf16 hi/lo split operands
__device__ uint4 g_xh   [MROWS * DIM / 8];     // x        [r][k]
__device__ uint4 g_xl   [MROWS * DIM / 8];
__device__ uint4 g_wch  [3 * DIM * DIM / 8];   // Wcat     [e][k] (q,k,v stacked)
__device__ uint4 g_wcl  [3 * DIM * DIM / 8];
__device__ uint4 g_wh   [NSEQ * NSEQ / 8];     // exp(pos_bias) [t][j]
__device__ uint4 g_wl   [NSEQ * NSEQ / 8];
__device__ uint4 g_ekvTh[BSZ * DIM * NSEQ / 8];// (ek*v)^T [b][d][j]
__device__ uint4 g_ekvTl[BSZ * DIM * NSEQ / 8];
__device__ uint4 g_ekTh [BSZ * DIM * NSEQ / 8];// ek^T     [b][d][j]
__device__ uint4 g_ekTl [BSZ * DIM * NSEQ / 8];

// ---------------------------------------------------------------------------
__device__ __forceinline__ uint32_t smem_u32(const void* p) {
    uint32_t a;
    asm("{ .reg .u64 t; cvta.to.shared.u64 t, %1; cvt.u32.u64 %0, t; }"
        : "=r"(a) : "l"(p));
    return a;
}
#define LDSM_X4(r0, r1, r2, r3, addr) \
    asm volatile("ldmatrix.sync.aligned.m8n8.x4.shared.b16 {%0,%1,%2,%3}, [%4];" \
        : "=r"(r0), "=r"(r1), "=r"(r2), "=r"(r3) : "r"(addr))

#define MMA16816(d, a, b0, b1) \
    asm volatile("mma.sync.aligned.m16n8k16.row.col.f32.bf16.bf16.f32 " \
        "{%0,%1,%2,%3}, {%4,%5,%6,%7}, {%8,%9}, {%0,%1,%2,%3};" \
        : "+f"((d)[0]), "+f"((d)[1]), "+f"((d)[2]), "+f"((d)[3]) \
        : "r"((a)[0]), "r"((a)[1]), "r"((a)[2]), "r"((a)[3]), \
          "r"(b0), "r"(b1))

__device__ __forceinline__ void bsplit(float x, unsigned short& h, unsigned short& l) {
    __nv_bfloat16 hb = __float2bfloat16(x);
    __nv_bfloat16 lb = __float2bfloat16(x - __bfloat162float(hb));
    h = __bfloat16_as_ushort(hb);
    l = __bfloat16_as_ushort(lb);
}

// shared fragment geometry (64-row tiles, 32 bf16 per row chunk)
#define SA_HI 0
#define SA_LO 5120
#define SB_HI 10240
#define SB_LO 15360
#define HLOFF 5120
#define RSTRIDE 80
#define BUFSZ 20480

// ---------------------------------------------------------------------------
// Kernel 0: split x and Wcat into bf16 hi/lo.
// items: x 131072 float2 + Wcat 24576 float2 = 155648 -> grid 608 x 256
// ---------------------------------------------------------------------------
__global__ __launch_bounds__(256)
void prep_xw_kernel(const float* __restrict__ x,
                    const float* __restrict__ Wq,
                    const float* __restrict__ Wk,
                    const float* __restrict__ Wv)
{
    int i = blockIdx.x * 256 + threadIdx.x;
    if (i < MROWS * DIM / 2) {
        float2 p = reinterpret_cast<const float2*>(x)[i];
        unsigned short h0, l0, h1, l1;
        bsplit(p.x, h0, l0); bsplit(p.y, h1, l1);
        reinterpret_cast<uint32_t*>(g_xh)[i] = ((uint32_t)h1 << 16) | h0;
        reinterpret_cast<uint32_t*>(g_xl)[i] = ((uint32_t)l1 << 16) | l0;
    } else {
        int j = i - MROWS * DIM / 2;           // 0..24575 over [384][64]
        if (j >= 3 * DIM * DIM / 2) return;
        int row = j >> 6, c2 = j & 63;
        int m = row >> 7, rr = row & 127;
        const float* W = (m == 0) ? Wq : (m == 1) ? Wk : Wv;
        float2 p = reinterpret_cast<const float2*>(W + rr * DIM)[c2];
        unsigned short h0, l0, h1, l1;
        bsplit(p.x, h0, l0); bsplit(p.y, h1, l1);
        reinterpret_cast<uint32_t*>(g_wch)[row * 64 + c2] = ((uint32_t)h1 << 16) | h0;
        reinterpret_cast<uint32_t*>(g_wcl)[row * 64 + c2] = ((uint32_t)l1 << 16) | l0;
    }
}

// ---------------------------------------------------------------------------
// Kernel 1: projections on mma.sync. C[2048, 384] = x @ Wcat^T, K=128.
// Block 64r x 64e, 8 warps (32r x 16e), 4 K-chunks of 32, double-buffered.
// Grid dim3(6, 32): et = bIdx.x (matrix m = et>>1), rt = bIdx.y.
// Epilogue: +bias, m0 sigmoid -> g_q, m1 exp -> g_ek, m2 id -> g_vraw.
// ---------------------------------------------------------------------------
__global__ __launch_bounds__(256)
void proj_mma_kernel(const float* __restrict__ bq,
                     const float* __restrict__ bk,
                     const float* __restrict__ bv)
{
    __shared__ __align__(16) char sm[2 * BUFSZ];
    const uint32_t smem = smem_u32(sm);

    const int tid  = threadIdx.x;
    const int wid  = tid >> 5, lane = tid & 31;
    const int et   = blockIdx.x;          // 0..5
    const int rt   = blockIdx.y;          // 0..31
    const int m    = et >> 1;
    const int r0   = rt * 64;
    const int e0   = et * 64;             // global Wcat row

    const float* __restrict__ bias = (m == 0) ? bq : (m == 1) ? bk : bv;
    float* __restrict__ outp       = (m == 0) ? g_q : (m == 1) ? g_ek : g_vraw;

    const int srow = tid >> 2, sseg = tid & 3;
    const uint32_t soff = (uint32_t)(srow * RSTRIDE + sseg * 16);
    const int a_g = (r0 + srow) * 16 + sseg;     // x rows, 16 uint4/row
    const int b_g = (e0 + srow) * 16 + sseg;     // Wcat rows

    const int wm = wid & 1, wn = wid >> 1;
    const int r  = lane & 7, sel = lane >> 3;

    uint32_t aoff[2][2], boff[2];
    #pragma unroll
    for (int mt = 0; mt < 2; ++mt)
        #pragma unroll
        for (int ks = 0; ks < 2; ++ks) {
            int row = wm * 32 + mt * 16 + r + (sel & 1) * 8;
            aoff[mt][ks] = smem + SA_HI + row * RSTRIDE + ((sel >> 1) * 16) + ks * 32;
        }
    #pragma unroll
    for (int ks = 0; ks < 2; ++ks) {
        int row = wn * 16 + r + (sel >> 1) * 8;
        boff[ks] = smem + SB_HI + row * RSTRIDE + ((sel & 1) * 16) + ks * 32;
    }

    float acc[2][2][4] = {};

    uint4 pAh = g_xh[a_g], pAl = g_xl[a_g], pBh = g_wch[b_g], pBl = g_wcl[b_g];
    *reinterpret_cast<uint4*>(sm + SA_HI + soff) = pAh;
    *reinterpret_cast<uint4*>(sm + SA_LO + soff) = pAl;
    *reinterpret_cast<uint4*>(sm + SB_HI + soff) = pBh;
    *reinterpret_cast<uint4*>(sm + SB_LO + soff) = pBl;
    __syncthreads();

    for (int c = 0; c < 4; ++c) {
        const uint32_t bo = (uint32_t)(c & 1) * BUFSZ;
        if (c < 3) {
            int gi = (c + 1) * 4;
            pAh = g_xh[a_g + gi];  pAl = g_xl[a_g + gi];
            pBh = g_wch[b_g + gi]; pBl = g_wcl[b_g + gi];
        }
        #pragma unroll
        for (int ks = 0; ks < 2; ++ks) {
            uint32_t aH[2][4], aL[2][4], bH[4], bL[4];
            LDSM_X4(aH[0][0], aH[0][1], aH[0][2], aH[0][3], aoff[0][ks] + bo);
            LDSM_X4(aH[1][0], aH[1][1], aH[1][2], aH[1][3], aoff[1][ks] + bo);
            LDSM_X4(aL[0][0], aL[0][1], aL[0][2], aL[0][3], aoff[0][ks] + bo + HLOFF);
            LDSM_X4(aL[1][0], aL[1][1], aL[1][2], aL[1][3], aoff[1][ks] + bo + HLOFF);
            LDSM_X4(bH[0], bH[1], bH[2], bH[3], boff[ks] + bo);
            LDSM_X4(bL[0], bL[1], bL[2], bL[3], boff[ks] + bo + HLOFF);
            #pragma unroll
            for (int mt = 0; mt < 2; ++mt)
                #pragma unroll
                for (int nt = 0; nt < 2; ++nt) {
                    MMA16816(acc[mt][nt], aH[mt], bH[nt * 2], bH[nt * 2 + 1]);
                    MMA16816(acc[mt][nt], aH[mt], bL[nt * 2], bL[nt * 2 + 1]);
                    MMA16816(acc[mt][nt], aL[mt], bH[nt * 2], bH[nt * 2 + 1]);
                }
        }
        if (c < 3) {
            const uint32_t nb = (uint32_t)((c + 1) & 1) * BUFSZ;
            *reinterpret_cast<uint4*>(sm + nb + SA_HI + soff) = pAh;
            *reinterpret_cast<uint4*>(sm + nb + SA_LO + soff) = pAl;
            *reinterpret_cast<uint4*>(sm + nb + SB_HI + soff) = pBh;
            *reinterpret_cast<uint4*>(sm + nb + SB_LO + soff) = pBl;
        }
        __syncthreads();
    }

    const int g  = lane >> 2;
    const int t2 = (lane & 3) * 2;
    #pragma unroll
    for (int mt = 0; mt < 2; ++mt)
        #pragma unroll
        for (int nt = 0; nt < 2; ++nt) {
            int trow = r0 + wm * 32 + mt * 16 + g;
            int ew   = (et & 1) * 64 + wn * 16 + nt * 8 + t2;   // 0..127 within matrix
            float b0 = bias[ew], b1 = bias[ew + 1];
            #pragma unroll
            for (int hh = 0; hh < 2; ++hh) {                    // rows g, g+8
                float v0 = acc[mt][nt][hh * 2 + 0] + b0;
                float v1 = acc[mt][nt][hh * 2 + 1] + b1;
                if (m == 0)      { v0 = 1.0f / (1.0f + expf(-v0)); v1 = 1.0f / (1.0f + expf(-v1)); }
                else if (m == 1) { v0 = expf(v0); v1 = expf(v1); }
                *reinterpret_cast<float2*>(&outp[(size_t)(trow + hh * 8) * DIM + ew]) =
                    make_float2(v0, v1);
            }
        }
}

// ---------------------------------------------------------------------------
// Kernel 2: merged prep — blocks [0,512): exp(pos_bias) split;
//                         blocks [512,768): transpose-split ek/ekv.
// ---------------------------------------------------------------------------
__global__ __launch_bounds__(256)
void prep_all_kernel(const float* __restrict__ pos_bias)
{
    __shared__ float s_ek[32][33], s_v[32][33];
    const int tid = threadIdx.x;

    if (blockIdx.x < 512) {
        int i = blockIdx.x * 256 + tid;                  // 131072 float2
        float2 p = reinterpret_cast<const float2*>(pos_bias)[i];
        float e0 = expf(p.x), e1 = expf(p.y);
        unsigned short h0, l0, h1, l1;
        bsplit(e0, h0, l0); bsplit(e1, h1, l1);
        reinterpret_cast<uint32_t*>(g_wh)[i] = ((uint32_t)h1 << 16) | h0;
        reinterpret_cast<uint32_t*>(g_wl)[i] = ((uint32_t)l1 << 16) | l0;
        return;
    }

    const int bx = blockIdx.x - 512;
    const int jt = bx & 15, dt = (bx >> 4) & 3, b = bx >> 6;
    const int j0 = jt * 32, d0 = dt * 32;

    const float* __restrict__ ekp = g_ek   + b * NSEQ * DIM;
    const float* __restrict__ vp  = g_vraw + b * NSEQ * DIM;

    for (int i = tid; i < 1024; i += 256) {
        int jj = i >> 5, dd = i & 31;
        s_ek[jj][dd] = ekp[(j0 + jj) * DIM + d0 + dd];
        s_v [jj][dd] = vp [(j0 + jj) * DIM + d0 + dd];
    }
    __syncthreads();

    for (int i = tid; i < 512; i += 256) {
        int dd = i >> 4, jj = (i & 15) * 2;
        float ek0 = s_ek[jj][dd],     ek1 = s_ek[jj + 1][dd];
        float v0  = s_v [jj][dd],     v1  = s_v [jj + 1][dd];
        float ekv0 = ek0 * v0, ekv1 = ek1 * v1;
        unsigned short kh0, kl0, kh1, kl1, vh0, vl0, vh1, vl1;
        bsplit(ek0,  kh0, kl0);  bsplit(ek1,  kh1, kl1);
        bsplit(ekv0, vh0, vl0);  bsplit(ekv1, vh1, vl1);
        uint32_t u32i = (((b * DIM + d0 + dd) * NSEQ) + j0 + jj) >> 1;
        reinterpret_cast<uint32_t*>(g_ekTh )[u32i] = ((uint32_t)kh1 << 16) | kh0;
        reinterpret_cast<uint32_t*>(g_ekTl )[u32i] = ((uint32_t)kl1 << 16) | kl0;
        reinterpret_cast<uint32_t*>(g_ekvTh)[u32i] = ((uint32_t)vh1 << 16) | vh0;
        reinterpret_cast<uint32_t*>(g_ekvTl)[u32i] = ((uint32_t)vl1 << 16) | vl0;
    }
}

// ---------------------------------------------------------------------------
// Kernel 3: AFT core on mma.sync, double-buffered smem (one sync per chunk).
// Block 64t x 64n, K=512 in 16 chunks of 32. Grid 128.
// ---------------------------------------------------------------------------
__global__ __launch_bounds__(256)
void aft_mma_kernel()
{
    __shared__ __align__(16) char sm[2 * BUFSZ];
    const uint32_t smem = smem_u32(sm);

    const int tid  = threadIdx.x;
    const int wid  = tid >> 5, lane = tid & 31;
    const int bx   = blockIdx.x;
    const int b    = bx & 3;
    const int tt   = (bx >> 2) & 7;
    const int qq   = bx >> 5;
    const int ct   = qq >> 1;
    const int dh   = qq & 1;
    const int t0   = tt * 64;
    const int d0   = dh * 64;

    const uint4* __restrict__ Ah = g_wh;
    const uint4* __restrict__ Al = g_wl;
    const uint4* __restrict__ Bh = ct ? g_ekTh : g_ekvTh;
    const uint4* __restrict__ Bl = ct ? g_ekTl : g_ekvTl;
    float* __restrict__ outp     = ct ? g_den  : g_num;

    const int srow = tid >> 2, sseg = tid & 3;
    const uint32_t soff = (uint32_t)(srow * RSTRIDE + sseg * 16);
    const int a_g = (t0 + srow) * (NSEQ / 8) + sseg;
    const int b_g = (b * DIM + d0 + srow) * (NSEQ / 8) + sseg;

    const int wm = wid & 1, wn = wid >> 1;
    const int r  = lane & 7, sel = lane >> 3;

    uint32_t aoff[2][2], boff[2];
    #pragma unroll
    for (int mt = 0; mt < 2; ++mt)
        #pragma unroll
        for (int ks = 0; ks < 2; ++ks) {
            int row = wm * 32 + mt * 16 + r + (sel & 1) * 8;
            aoff[mt][ks] = smem + SA_HI + row * RSTRIDE + ((sel >> 1) * 16) + ks * 32;
        }
    #pragma unroll
    for (int ks = 0; ks < 2; ++ks) {
        int row = wn * 16 + r + (sel >> 1) * 8;
        boff[ks] = smem + SB_HI + row * RSTRIDE + ((sel & 1) * 16) + ks * 32;
    }

    float acc[2][2][4] = {};

    uint4 pAh = Ah[a_g], pAl = Al[a_g], pBh = Bh[b_g], pBl = Bl[b_g];
    *reinterpret_cast<uint4*>(sm + SA_HI + soff) = pAh;
    *reinterpret_cast<uint4*>(sm + SA_LO + soff) = pAl;
    *reinterpret_cast<uint4*>(sm + SB_HI + soff) = pBh;
    *reinterpret_cast<uint4*>(sm + SB_LO + soff) = pBl;
    __syncthreads();

    for (int c = 0; c < 16; ++c) {
        const uint32_t bo = (uint32_t)(c & 1) * BUFSZ;
        if (c < 15) {
            int gi = (c + 1) * 4;
            pAh = Ah[a_g + gi];  pAl = Al[a_g + gi];
            pBh = Bh[b_g + gi];  pBl = Bl[b_g + gi];
        }
        #pragma unroll
        for (int ks = 0; ks < 2; ++ks) {
            uint32_t aH[2][4], aL[2][4], bH[4], bL[4];
            LDSM_X4(aH[0][0], aH[0][1], aH[0][2], aH[0][3], aoff[0][ks] + bo);
            LDSM_X4(aH[1][0], aH[1][1], aH[1][2], aH[1][3], aoff[1][ks] + bo);
            LDSM_X4(aL[0][0], aL[0][1], aL[0][2], aL[0][3], aoff[0][ks] + bo + HLOFF);
            LDSM_X4(aL[1][0], aL[1][1], aL[1][2], aL[1][3], aoff[1][ks] + bo + HLOFF);
            LDSM_X4(bH[0], bH[1], bH[2], bH[3], boff[ks] + bo);
            LDSM_X4(bL[0], bL[1], bL[2], bL[3], boff[ks] + bo + HLOFF);
            #pragma unroll
            for (int mt = 0; mt < 2; ++mt)
                #pragma unroll
                for (int nt = 0; nt < 2; ++nt) {
                    MMA16816(acc[mt][nt], aH[mt], bH[nt * 2], bH[nt * 2 + 1]);
                    MMA16816(acc[mt][nt], aH[mt], bL[nt * 2], bL[nt * 2 + 1]);
                    MMA16816(acc[mt][nt], aL[mt], bH[nt * 2], bH[nt * 2 + 1]);
                }
        }
        if (c < 15) {
            const uint32_t nb = (uint32_t)((c + 1) & 1) * BUFSZ;
            *reinterpret_cast<uint4*>(sm + nb + SA_HI + soff) = pAh;
            *reinterpret_cast<uint4*>(sm + nb + SA_LO + soff) = pAl;
            *reinterpret_cast<uint4*>(sm + nb + SB_HI + soff) = pBh;
            *reinterpret_cast<uint4*>(sm + nb + SB_LO + soff) = pBl;
        }
        __syncthreads();
    }

    const int g  = lane >> 2;
    const int t2 = (lane & 3) * 2;
    #pragma unroll
    for (int mt = 0; mt < 2; ++mt)
        #pragma unroll
        for (int nt = 0; nt < 2; ++nt) {
            int trow = t0 + wm * 32 + mt * 16 + g;
            int dcol = d0 + wn * 16 + nt * 8 + t2;
            size_t base = ((size_t)(b * NSEQ + trow)) * DIM + dcol;
            *reinterpret_cast<float2*>(&outp[base]) =
                make_float2(acc[mt][nt][0], acc[mt][nt][1]);
            *reinterpret_cast<float2*>(&outp[base + 8 * DIM]) =
                make_float2(acc[mt][nt][2], acc[mt][nt][3]);
        }
}

// ---------------------------------------------------------------------------
// Kernel 4: finalize — out = q * num / den
// ---------------------------------------------------------------------------
__global__ __launch_bounds__(256)
void finalize_kernel(float* __restrict__ out)
{
    int i = blockIdx.x * 256 + threadIdx.x;
    float4 n = reinterpret_cast<const float4*>(g_num)[i];
    float4 d = reinterpret_cast<const float4*>(g_den)[i];
    float4 q = reinterpret_cast<const float4*>(g_q)[i];
    reinterpret_cast<float4*>(out)[i] = make_float4(
        q.x * (n.x / d.x), q.y * (n.y / d.y),
        q.z * (n.z / d.z), q.w * (n.w / d.w));
}

// ---------------------------------------------------------------------------
extern "C" void kernel_launch(void* const* d_in, const int* in_sizes, int n_in,
                              void* d_out, int out_size)
{
    const float* x        = (const float*)d_in[0];
    const float* Wq       = (const float*)d_in[1];
    const float* bq       = (const float*)d_in[2];
    const float* Wk       = (const float*)d_in[3];
    const float* bk       = (const float*)d_in[4];
    const float* Wv       = (const float*)d_in[5];
    const float* bv       = (const float*)d_in[6];
    const float* pos_bias = (const float*)d_in[7];
    float* out = (float*)d_out;

    prep_xw_kernel<<<608, 256>>>(x, Wq, Wk, Wv);
    proj_mma_kernel<<<dim3(6, 32), 256>>>(bq, bk, bv);
    prep_all_kernel<<<768, 256>>>(pos_bias);
    aft_mma_kernel<<<128, 256>>>();
    finalize_kernel<<<256, 256>>>(out);
}

// round 13
// speedup vs baseline: 4.3341x; 1.0767x over previous
#include <cuda_runtime.h>
#include <cuda_bf16.h>
#include <math.h>
#include <stdint.h>

#define BSZ  4
#define NSEQ 512
#define DIM  128
#define MROWS (BSZ * NSEQ)      // 2048
#define KSPLIT 4

// ---- scratch (__device__ globals; no cudaMalloc allowed) -------------------
__device__ float g_q   [MROWS * DIM];
__device__ float g_ek  [MROWS * DIM];
__device__ float g_vraw[MROWS * DIM];
__device__ float g_pnum[KSPLIT * MROWS * DIM];   // per-ksl partial numerators
__device__ float g_pden[KSPLIT * MROWS * DIM];   // per-ksl partial denominators

// bf16 hi/lo split operands
__device__ uint4 g_xh   [MROWS * DIM / 8];
__device__ uint4 g_xl   [MROWS * DIM / 8];
__device__ uint4 g_wch  [3 * DIM * DIM / 8];
__device__ uint4 g_wcl  [3 * DIM * DIM / 8];
__device__ uint4 g_wh   [NSEQ * NSEQ / 8];
__device__ uint4 g_wl   [NSEQ * NSEQ / 8];
__device__ uint4 g_ekvTh[BSZ * DIM * NSEQ / 8];
__device__ uint4 g_ekvTl[BSZ * DIM * NSEQ / 8];
__device__ uint4 g_ekTh [BSZ * DIM * NSEQ / 8];
__device__ uint4 g_ekTl [BSZ * DIM * NSEQ / 8];

// ---------------------------------------------------------------------------
__device__ __forceinline__ uint32_t smem_u32(const void* p) {
    uint32_t a;
    asm("{ .reg .u64 t; cvta.to.shared.u64 t, %1; cvt.u32.u64 %0, t; }"
        : "=r"(a) : "l"(p));
    return a;
}
#define LDSM_X4(r0, r1, r2, r3, addr) \
    asm volatile("ldmatrix.sync.aligned.m8n8.x4.shared.b16 {%0,%1,%2,%3}, [%4];" \
        : "=r"(r0), "=r"(r1), "=r"(r2), "=r"(r3) : "r"(addr))

#define MMA16816(d, a, b0, b1) \
    asm volatile("mma.sync.aligned.m16n8k16.row.col.f32.bf16.bf16.f32 " \
        "{%0,%1,%2,%3}, {%4,%5,%6,%7}, {%8,%9}, {%0,%1,%2,%3};" \
        : "+f"((d)[0]), "+f"((d)[1]), "+f"((d)[2]), "+f"((d)[3]) \
        : "r"((a)[0]), "r"((a)[1]), "r"((a)[2]), "r"((a)[3]), \
          "r"(b0), "r"(b1))

__device__ __forceinline__ void cp16(uint32_t saddr, const void* gptr) {
    asm volatile("cp.async.cg.shared.global [%0], [%1], 16;"
                 :: "r"(saddr), "l"(gptr));
}
__device__ __forceinline__ void cp_commit() {
    asm volatile("cp.async.commit_group;" ::: "memory");
}
__device__ __forceinline__ void cp_wait0() {
    asm volatile("cp.async.wait_group 0;" ::: "memory");
}

__device__ __forceinline__ void bsplit(float x, unsigned short& h, unsigned short& l) {
    __nv_bfloat16 hb = __float2bfloat16(x);
    __nv_bfloat16 lb = __float2bfloat16(x - __bfloat162float(hb));
    h = __bfloat16_as_ushort(hb);
    l = __bfloat16_as_ushort(lb);
}

// geometry (proj kernel: 64-row A/B tiles; aft kernel: 64-row A + 128-row B)
#define RSTRIDE 80
#define PSA_HI 0
#define PSA_LO 5120
#define PSB_HI 10240
#define PSB_LO 15360
#define PBUFSZ 20480
// aft layout
#define ASA_HI 0
#define ASA_LO 5120
#define ASB_HI 10240
#define ASB_LO 20480
#define ABUFSZ 30720
#define AFT_SMEM (2 * ABUFSZ)   // 61440

// ---------------------------------------------------------------------------
// Kernel 0: split x and Wcat into bf16 hi/lo. (unchanged from R8)
// ---------------------------------------------------------------------------
__global__ __launch_bounds__(256)
void prep_xw_kernel(const float* __restrict__ x,
                    const float* __restrict__ Wq,
                    const float* __restrict__ Wk,
                    const float* __restrict__ Wv)
{
    int i = blockIdx.x * 256 + threadIdx.x;
    if (i < MROWS * DIM / 2) {
        float2 p = reinterpret_cast<const float2*>(x)[i];
        unsigned short h0, l0, h1, l1;
        bsplit(p.x, h0, l0); bsplit(p.y, h1, l1);
        reinterpret_cast<uint32_t*>(g_xh)[i] = ((uint32_t)h1 << 16) | h0;
        reinterpret_cast<uint32_t*>(g_xl)[i] = ((uint32_t)l1 << 16) | l0;
    } else {
        int j = i - MROWS * DIM / 2;
        if (j >= 3 * DIM * DIM / 2) return;
        int row = j >> 6, c2 = j & 63;
        int m = row >> 7, rr = row & 127;
        const float* W = (m == 0) ? Wq : (m == 1) ? Wk : Wv;
        float2 p = reinterpret_cast<const float2*>(W + rr * DIM)[c2];
        unsigned short h0, l0, h1, l1;
        bsplit(p.x, h0, l0); bsplit(p.y, h1, l1);
        reinterpret_cast<uint32_t*>(g_wch)[row * 64 + c2] = ((uint32_t)h1 << 16) | h0;
        reinterpret_cast<uint32_t*>(g_wcl)[row * 64 + c2] = ((uint32_t)l1 << 16) | l0;
    }
}

// ---------------------------------------------------------------------------
// Kernel 1: projections on mma.sync (unchanged from R8 — measured good)
// ---------------------------------------------------------------------------
__global__ __launch_bounds__(256)
void proj_mma_kernel(const float* __restrict__ bq,
                     const float* __restrict__ bk,
                     const float* __restrict__ bv)
{
    __shared__ __align__(16) char sm[2 * PBUFSZ];
    const uint32_t smem = smem_u32(sm);

    const int tid  = threadIdx.x;
    const int wid  = tid >> 5, lane = tid & 31;
    const int et   = blockIdx.x;
    const int rt   = blockIdx.y;
    const int m    = et >> 1;
    const int r0   = rt * 64;
    const int e0   = et * 64;

    const float* __restrict__ bias = (m == 0) ? bq : (m == 1) ? bk : bv;
    float* __restrict__ outp       = (m == 0) ? g_q : (m == 1) ? g_ek : g_vraw;

    const int srow = tid >> 2, sseg = tid & 3;
    const uint32_t soff = (uint32_t)(srow * RSTRIDE + sseg * 16);
    const int a_g = (r0 + srow) * 16 + sseg;
    const int b_g = (e0 + srow) * 16 + sseg;

    const int wm = wid & 1, wn = wid >> 1;
    const int r  = lane & 7, sel = lane >> 3;

    uint32_t aoff[2][2], boff[2];
    #pragma unroll
    for (int mt = 0; mt < 2; ++mt)
        #pragma unroll
        for (int ks = 0; ks < 2; ++ks) {
            int row = wm * 32 + mt * 16 + r + (sel & 1) * 8;
            aoff[mt][ks] = smem + PSA_HI + row * RSTRIDE + ((sel >> 1) * 16) + ks * 32;
        }
    #pragma unroll
    for (int ks = 0; ks < 2; ++ks) {
        int row = wn * 16 + r + (sel >> 1) * 8;
        boff[ks] = smem + PSB_HI + row * RSTRIDE + ((sel & 1) * 16) + ks * 32;
    }

    float acc[2][2][4] = {};

    uint4 pAh = g_xh[a_g], pAl = g_xl[a_g], pBh = g_wch[b_g], pBl = g_wcl[b_g];
    *reinterpret_cast<uint4*>(sm + PSA_HI + soff) = pAh;
    *reinterpret_cast<uint4*>(sm + PSA_LO + soff) = pAl;
    *reinterpret_cast<uint4*>(sm + PSB_HI + soff) = pBh;
    *reinterpret_cast<uint4*>(sm + PSB_LO + soff) = pBl;
    __syncthreads();

    for (int c = 0; c < 4; ++c) {
        const uint32_t bo = (uint32_t)(c & 1) * PBUFSZ;
        if (c < 3) {
            int gi = (c + 1) * 4;
            pAh = g_xh[a_g + gi];  pAl = g_xl[a_g + gi];
            pBh = g_wch[b_g + gi]; pBl = g_wcl[b_g + gi];
        }
        #pragma unroll
        for (int ks = 0; ks < 2; ++ks) {
            uint32_t aH[2][4], aL[2][4], bH[4], bL[4];
            LDSM_X4(aH[0][0], aH[0][1], aH[0][2], aH[0][3], aoff[0][ks] + bo);
            LDSM_X4(aH[1][0], aH[1][1], aH[1][2], aH[1][3], aoff[1][ks] + bo);
            LDSM_X4(aL[0][0], aL[0][1], aL[0][2], aL[0][3], aoff[0][ks] + bo + PSA_LO);
            LDSM_X4(aL[1][0], aL[1][1], aL[1][2], aL[1][3], aoff[1][ks] + bo + PSA_LO);
            LDSM_X4(bH[0], bH[1], bH[2], bH[3], boff[ks] + bo);
            LDSM_X4(bL[0], bL[1], bL[2], bL[3], boff[ks] + bo + PSA_LO);
            #pragma unroll
            for (int mt = 0; mt < 2; ++mt)
                #pragma unroll
                for (int nt = 0; nt < 2; ++nt) {
                    MMA16816(acc[mt][nt], aH[mt], bH[nt * 2], bH[nt * 2 + 1]);
                    MMA16816(acc[mt][nt], aH[mt], bL[nt * 2], bL[nt * 2 + 1]);
                    MMA16816(acc[mt][nt], aL[mt], bH[nt * 2], bH[nt * 2 + 1]);
                }
        }
        if (c < 3) {
            const uint32_t nb = (uint32_t)((c + 1) & 1) * PBUFSZ;
            *reinterpret_cast<uint4*>(sm + nb + PSA_HI + soff) = pAh;
            *reinterpret_cast<uint4*>(sm + nb + PSA_LO + soff) = pAl;
            *reinterpret_cast<uint4*>(sm + nb + PSB_HI + soff) = pBh;
            *reinterpret_cast<uint4*>(sm + nb + PSB_LO + soff) = pBl;
        }
        __syncthreads();
    }

    const int g  = lane >> 2;
    const int t2 = (lane & 3) * 2;
    #pragma unroll
    for (int mt = 0; mt < 2; ++mt)
        #pragma unroll
        for (int nt = 0; nt < 2; ++nt) {
            int trow = r0 + wm * 32 + mt * 16 + g;
            int ew   = (et & 1) * 64 + wn * 16 + nt * 8 + t2;
            float b0 = bias[ew], b1 = bias[ew + 1];
            #pragma unroll
            for (int hh = 0; hh < 2; ++hh) {
                float v0 = acc[mt][nt][hh * 2 + 0] + b0;
                float v1 = acc[mt][nt][hh * 2 + 1] + b1;
                if (m == 0)      { v0 = 1.0f / (1.0f + expf(-v0)); v1 = 1.0f / (1.0f + expf(-v1)); }
                else if (m == 1) { v0 = expf(v0); v1 = expf(v1); }
                *reinterpret_cast<float2*>(&outp[(size_t)(trow + hh * 8) * DIM + ew]) =
                    make_float2(v0, v1);
            }
        }
}

// ---------------------------------------------------------------------------
// Kernel 2: merged prep (unchanged from R8)
// ---------------------------------------------------------------------------
__global__ __launch_bounds__(256)
void prep_all_kernel(const float* __restrict__ pos_bias)
{
    __shared__ float s_ek[32][33], s_v[32][33];
    const int tid = threadIdx.x;

    if (blockIdx.x < 512) {
        int i = blockIdx.x * 256 + tid;
        float2 p = reinterpret_cast<const float2*>(pos_bias)[i];
        float e0 = expf(p.x), e1 = expf(p.y);
        unsigned short h0, l0, h1, l1;
        bsplit(e0, h0, l0); bsplit(e1, h1, l1);
        reinterpret_cast<uint32_t*>(g_wh)[i] = ((uint32_t)h1 << 16) | h0;
        reinterpret_cast<uint32_t*>(g_wl)[i] = ((uint32_t)l1 << 16) | l0;
        return;
    }

    const int bx = blockIdx.x - 512;
    const int jt = bx & 15, dt = (bx >> 4) & 3, b = bx >> 6;
    const int j0 = jt * 32, d0 = dt * 32;

    const float* __restrict__ ekp = g_ek   + b * NSEQ * DIM;
    const float* __restrict__ vp  = g_vraw + b * NSEQ * DIM;

    for (int i = tid; i < 1024; i += 256) {
        int jj = i >> 5, dd = i & 31;
        s_ek[jj][dd] = ekp[(j0 + jj) * DIM + d0 + dd];
        s_v [jj][dd] = vp [(j0 + jj) * DIM + d0 + dd];
    }
    __syncthreads();

    for (int i = tid; i < 512; i += 256) {
        int dd = i >> 4, jj = (i & 15) * 2;
        float ek0 = s_ek[jj][dd],     ek1 = s_ek[jj + 1][dd];
        float v0  = s_v [jj][dd],     v1  = s_v [jj + 1][dd];
        float ekv0 = ek0 * v0, ekv1 = ek1 * v1;
        unsigned short kh0, kl0, kh1, kl1, vh0, vl0, vh1, vl1;
        bsplit(ek0,  kh0, kl0);  bsplit(ek1,  kh1, kl1);
        bsplit(ekv0, vh0, vl0);  bsplit(ekv1, vh1, vl1);
        uint32_t u32i = (((b * DIM + d0 + dd) * NSEQ) + j0 + jj) >> 1;
        reinterpret_cast<uint32_t*>(g_ekTh )[u32i] = ((uint32_t)kh1 << 16) | kh0;
        reinterpret_cast<uint32_t*>(g_ekTl )[u32i] = ((uint32_t)kl1 << 16) | kl0;
        reinterpret_cast<uint32_t*>(g_ekvTh)[u32i] = ((uint32_t)vh1 << 16) | vh0;
        reinterpret_cast<uint32_t*>(g_ekvTl)[u32i] = ((uint32_t)vl1 << 16) | vl0;
    }
}

// ---------------------------------------------------------------------------
// Kernel 3: AFT core — fused num+den tile, 4-way K-split, cp.async pipeline.
// Block tile 64t x 128n (n = [ekv d-half | ek d-half]), K=128 in 4 chunks.
// 8 warps, warp tile 32t x 32n -> 8 acc tiles (2x ILP vs R11).
// Grid 256 = ksl(4) x b(4) x tt(8) x dh(2); partials to g_pnum/g_pden.
// ---------------------------------------------------------------------------
__global__ __launch_bounds__(256)
void aft_mma_kernel()
{
    extern __shared__ __align__(16) char sm[];
    const uint32_t smem = smem_u32(sm);

    const int tid  = threadIdx.x;
    const int wid  = tid >> 5, lane = tid & 31;
    const int bx   = blockIdx.x;
    const int ksl  = bx & 3;
    const int b    = (bx >> 2) & 3;
    const int tt   = (bx >> 4) & 7;
    const int dh   = (bx >> 7) & 1;
    const int t0   = tt * 64;
    const int d0   = dh * 64;
    const int j0u4 = ksl * 16;            // K-chunk start in uint4 units

    // ---- staging setup: 768 uint4-slots per buffer half, 3 per thread ----
    const uint4* srcH[3];
    const uint4* srcL[3];
    uint32_t shOff[3], slOff[3];
    int gb[3];
    #pragma unroll
    for (int k = 0; k < 3; ++k) {
        int i = tid + k * 256;
        int row = i >> 2, seg = i & 3;
        if (row < 64) {                    // A: w rows t0..t0+63
            srcH[k] = g_wh;  srcL[k] = g_wl;
            shOff[k] = ASA_HI + row * RSTRIDE + seg * 16;
            slOff[k] = ASA_LO + row * RSTRIDE + seg * 16;
            gb[k] = (t0 + row) * 64 + j0u4 + seg;
        } else {                           // B: n<64 ekv, n>=64 ek
            int n = row - 64;
            shOff[k] = ASB_HI + n * RSTRIDE + seg * 16;
            slOff[k] = ASB_LO + n * RSTRIDE + seg * 16;
            int dcol = (n < 64) ? (d0 + n) : (d0 + n - 64);
            srcH[k] = (n < 64) ? g_ekvTh : g_ekTh;
            srcL[k] = (n < 64) ? g_ekvTl : g_ekTl;
            gb[k] = (b * DIM + dcol) * 64 + j0u4 + seg;
        }
    }

    // ---- fragment addresses (relative; add buffer offset at use) ----
    const int wm = wid & 1, wn = wid >> 1;       // warp tile 32t x 32n
    const int r  = lane & 7, sel = lane >> 3;

    uint32_t aoff[2][2], boff[2][2];
    #pragma unroll
    for (int mt = 0; mt < 2; ++mt)
        #pragma unroll
        for (int ks = 0; ks < 2; ++ks) {
            int row = wm * 32 + mt * 16 + r + (sel & 1) * 8;
            aoff[mt][ks] = smem + ASA_HI + row * RSTRIDE + ((sel >> 1) * 16) + ks * 32;
        }
    #pragma unroll
    for (int ng = 0; ng < 2; ++ng)
        #pragma unroll
        for (int ks = 0; ks < 2; ++ks) {
            int row = wn * 32 + ng * 16 + r + (sel >> 1) * 8;
            boff[ng][ks] = smem + ASB_HI + row * RSTRIDE + ((sel & 1) * 16) + ks * 32;
        }

    float acc[2][4][4] = {};

    // ---- prologue: chunk 0 into buffer 0 ----
    #pragma unroll
    for (int k = 0; k < 3; ++k) {
        cp16(smem + shOff[k], srcH[k] + gb[k]);
        cp16(smem + slOff[k], srcL[k] + gb[k]);
    }
    cp_commit();
    cp_wait0();
    __syncthreads();

    for (int c = 0; c < 4; ++c) {
        const uint32_t bo = (uint32_t)(c & 1) * ABUFSZ;
        if (c < 3) {
            const uint32_t nb = (uint32_t)((c + 1) & 1) * ABUFSZ;
            int gi = (c + 1) * 4;
            #pragma unroll
            for (int k = 0; k < 3; ++k) {
                cp16(smem + nb + shOff[k], srcH[k] + gb[k] + gi);
                cp16(smem + nb + slOff[k], srcL[k] + gb[k] + gi);
            }
            cp_commit();
        }

        #pragma unroll
        for (int ks = 0; ks < 2; ++ks) {
            uint32_t aH[2][4], aL[2][4], bH[2][4], bL[2][4];
            LDSM_X4(aH[0][0], aH[0][1], aH[0][2], aH[0][3], aoff[0][ks] + bo);
            LDSM_X4(aH[1][0], aH[1][1], aH[1][2], aH[1][3], aoff[1][ks] + bo);
            LDSM_X4(aL[0][0], aL[0][1], aL[0][2], aL[0][3], aoff[0][ks] + bo + 5120);
            LDSM_X4(aL[1][0], aL[1][1], aL[1][2], aL[1][3], aoff[1][ks] + bo + 5120);
            LDSM_X4(bH[0][0], bH[0][1], bH[0][2], bH[0][3], boff[0][ks] + bo);
            LDSM_X4(bH[1][0], bH[1][1], bH[1][2], bH[1][3], boff[1][ks] + bo);
            LDSM_X4(bL[0][0], bL[0][1], bL[0][2], bL[0][3], boff[0][ks] + bo + 10240);
            LDSM_X4(bL[1][0], bL[1][1], bL[1][2], bL[1][3], boff[1][ks] + bo + 10240);

            #pragma unroll
            for (int mt = 0; mt < 2; ++mt)
                #pragma unroll
                for (int ng = 0; ng < 2; ++ng)
                    #pragma unroll
                    for (int sub = 0; sub < 2; ++sub) {
                        int nt = ng * 2 + sub;
                        MMA16816(acc[mt][nt], aH[mt], bH[ng][sub * 2], bH[ng][sub * 2 + 1]);
                        MMA16816(acc[mt][nt], aH[mt], bL[ng][sub * 2], bL[ng][sub * 2 + 1]);
                        MMA16816(acc[mt][nt], aL[mt], bH[ng][sub * 2], bH[ng][sub * 2 + 1]);
                    }
        }
        cp_wait0();
        __syncthreads();
    }

    // ---- epilogue: write partials ----
    const int g  = lane >> 2;
    const int t2 = (lane & 3) * 2;
    const size_t pbase = (size_t)(ksl * BSZ + b) * NSEQ;
    #pragma unroll
    for (int mt = 0; mt < 2; ++mt)
        #pragma unroll
        for (int nt = 0; nt < 4; ++nt) {
            int trow = t0 + wm * 32 + mt * 16 + g;
            int nl   = wn * 32 + nt * 8 + t2;
            float* dst = (nl < 64) ? g_pnum : g_pden;
            int d = d0 + ((nl < 64) ? nl : nl - 64);
            size_t base = (pbase + trow) * DIM + d;
            *reinterpret_cast<float2*>(&dst[base]) =
                make_float2(acc[mt][nt][0], acc[mt][nt][1]);
            *reinterpret_cast<float2*>(&dst[base + 8 * DIM]) =
                make_float2(acc[mt][nt][2], acc[mt][nt][3]);
        }
}

// ---------------------------------------------------------------------------
// Kernel 4: finalize — out = q * (sum_ksl pnum) / (sum_ksl pden)
// ---------------------------------------------------------------------------
__global__ __launch_bounds__(256)
void finalize_kernel(float* __restrict__ out)
{
    int i = blockIdx.x * 256 + threadIdx.x;     // 65536 float4
    const int STRIDE = MROWS * DIM / 4;         // 65536
    float4 n = make_float4(0.f, 0.f, 0.f, 0.f);
    float4 d = make_float4(0.f, 0.f, 0.f, 0.f);
    #pragma unroll
    for (int s = 0; s < KSPLIT; ++s) {
        float4 pn = reinterpret_cast<const float4*>(g_pnum)[s * STRIDE + i];
        float4 pd = reinterpret_cast<const float4*>(g_pden)[s * STRIDE + i];
        n.x += pn.x; n.y += pn.y; n.z += pn.z; n.w += pn.w;
        d.x += pd.x; d.y += pd.y; d.z += pd.z; d.w += pd.w;
    }
    float4 q = reinterpret_cast<const float4*>(g_q)[i];
    reinterpret_cast<float4*>(out)[i] = make_float4(
        q.x * (n.x / d.x), q.y * (n.y / d.y),
        q.z * (n.z / d.z), q.w * (n.w / d.w));
}

// ---------------------------------------------------------------------------
extern "C" void kernel_launch(void* const* d_in, const int* in_sizes, int n_in,
                              void* d_out, int out_size)
{
    const float* x        = (const float*)d_in[0];
    const float* Wq       = (const float*)d_in[1];
    const float* bq       = (const float*)d_in[2];
    const float* Wk       = (const float*)d_in[3];
    const float* bk       = (const float*)d_in[4];
    const float* Wv       = (const float*)d_in[5];
    const float* bv       = (const float*)d_in[6];
    const float* pos_bias = (const float*)d_in[7];
    float* out = (float*)d_out;

    cudaFuncSetAttribute(aft_mma_kernel,
                         cudaFuncAttributeMaxDynamicSharedMemorySize, AFT_SMEM);

    prep_xw_kernel<<<608, 256>>>(x, Wq, Wk, Wv);
    proj_mma_kernel<<<dim3(6, 32), 256>>>(bq, bk, bv);
    prep_all_kernel<<<768, 256>>>(pos_bias);
    aft_mma_kernel<<<256, 256, AFT_SMEM>>>();
    finalize_kernel<<<256, 256>>>(out);
}